// round 10
// baseline (speedup 1.0000x reference)
#include <cuda_runtime.h>
#include <cuda_bf16.h>

// CrossNet: B=500000, D=128, L=4.   out = alpha_L * x0 + beta_L
//   d_l = w_l·x0 ; alpha_{l+1} = alpha_l*(1+d_l) + c_l ; c_l = w_l·beta_l
//
// R10: persistent grid-stride version of R9. Exactly 148*4 blocks stay
// resident; each warp strides over 8-row groups. Removes the ~6 waves of
// block scheduling / wave-transition overhead that made R9's harness time
// (82us) worse than its ncu kernel time (76us). Inner body unchanged:
// 8-lane row teams (3 SHFL/row), weights+beta+c in SMEM, 8 rows front-
// batched per iteration (MLP=8 LDG.128/lane).

#define CN_L  4
#define CN_D  128

__global__ __launch_bounds__(256, 4) void crossnet_kernel(
    const float4* __restrict__ x,     // inputs  [B,128] as float4 [B,32]
    const float4* __restrict__ w4,    // kernels [L,128] as float4
    const float4* __restrict__ b4,    // biases
    float4*       __restrict__ out,
    int B, int totalWarps)
{
    __shared__ float4 ws[CN_L * 32];  // weights
    __shared__ float4 sbeta[32];      // beta_L
    __shared__ float  sc[CN_L];       // c_l

    const int tid = threadIdx.x;
    if (tid < CN_L * 32) ws[tid] = w4[tid];
    __syncthreads();

    // warp 0: compute beta_L and c_l into smem
    if (tid < 32) {
        const int ln = tid;
        float4 bt = make_float4(0.f, 0.f, 0.f, 0.f);
#pragma unroll
        for (int l = 0; l < CN_L; ++l) {
            const float4 wl = ws[l * 32 + ln];
            float p = wl.x * bt.x;
            p = fmaf(wl.y, bt.y, p);
            p = fmaf(wl.z, bt.z, p);
            p = fmaf(wl.w, bt.w, p);
#pragma unroll
            for (int off = 16; off > 0; off >>= 1)
                p += __shfl_xor_sync(0xffffffffu, p, off);
            if (ln == 0) sc[l] = p;
            const float4 bl = __ldg(&b4[l * 32 + ln]);
            bt.x += bl.x; bt.y += bl.y; bt.z += bl.z; bt.w += bl.w;
        }
        sbeta[ln] = bt;
    }
    __syncthreads();

    const int gwarp = (blockIdx.x * blockDim.x + tid) >> 5;
    const int lane  = tid & 31;
    const int sub   = lane >> 3;     // row within 4-row group (0..3)
    const int li    = lane & 7;      // lane within 8-lane row team

    float c[CN_L];
#pragma unroll
    for (int l = 0; l < CN_L; ++l) c[l] = sc[l];

    const long long stride = (long long)totalWarps * 8;

    // persistent stride loop: 8 rows (two 4-row sub-groups) per iteration
    for (long long row0 = (long long)gwarp * 8; row0 < B; row0 += stride) {
        const long long rA = row0 + sub;        // sub-group A row
        const long long rB = rA + 4;            // sub-group B row
        const bool okA = rA < B;
        const bool okB = rB < B;

        // 8 independent LDG.128 per lane, all front-batched
        float4 xa[4], xb[4];
#pragma unroll
        for (int i = 0; i < 4; ++i)
            xa[i] = okA ? __ldcs(&x[rA * 32 + i * 8 + li])
                        : make_float4(0.f, 0.f, 0.f, 0.f);
#pragma unroll
        for (int i = 0; i < 4; ++i)
            xb[i] = okB ? __ldcs(&x[rB * 32 + i * 8 + li])
                        : make_float4(0.f, 0.f, 0.f, 0.f);

        // partial dots over this lane's 16 cols (weights from smem)
        float pa[CN_L], pb[CN_L];
#pragma unroll
        for (int l = 0; l < CN_L; ++l) {
            float qa = 0.f, qb = 0.f;
#pragma unroll
            for (int i = 0; i < 4; ++i) {
                const float4 wv = ws[l * 32 + i * 8 + li];
                qa = fmaf(wv.x, xa[i].x, qa);  qb = fmaf(wv.x, xb[i].x, qb);
                qa = fmaf(wv.y, xa[i].y, qa);  qb = fmaf(wv.y, xb[i].y, qb);
                qa = fmaf(wv.z, xa[i].z, qa);  qb = fmaf(wv.z, xb[i].z, qb);
                qa = fmaf(wv.w, xa[i].w, qa);  qb = fmaf(wv.w, xb[i].w, qb);
            }
            pa[l] = qa; pb[l] = qb;
        }
        // 3-level butterfly within 8-lane teams; each SHFL serves 4 rows
#pragma unroll
        for (int off = 1; off < 8; off <<= 1) {
#pragma unroll
            for (int l = 0; l < CN_L; ++l) {
                pa[l] += __shfl_xor_sync(0xffffffffu, pa[l], off);
                pb[l] += __shfl_xor_sync(0xffffffffu, pb[l], off);
            }
        }

        // scalar alpha recurrences
        float aA = 1.0f, aB = 1.0f;
#pragma unroll
        for (int l = 0; l < CN_L; ++l) {
            aA = fmaf(aA, pa[l], aA + c[l]);
            aB = fmaf(aB, pb[l], aB + c[l]);
        }

        // epilogue
#pragma unroll
        for (int i = 0; i < 4; ++i) {
            const float4 bt = sbeta[i * 8 + li];
            if (okA) {
                float4 o;
                o.x = fmaf(xa[i].x, aA, bt.x);
                o.y = fmaf(xa[i].y, aA, bt.y);
                o.z = fmaf(xa[i].z, aA, bt.z);
                o.w = fmaf(xa[i].w, aA, bt.w);
                __stcs(&out[rA * 32 + i * 8 + li], o);
            }
            if (okB) {
                float4 o;
                o.x = fmaf(xb[i].x, aB, bt.x);
                o.y = fmaf(xb[i].y, aB, bt.y);
                o.z = fmaf(xb[i].z, aB, bt.z);
                o.w = fmaf(xb[i].w, aB, bt.w);
                __stcs(&out[rB * 32 + i * 8 + li], o);
            }
        }
    }
}

extern "C" void kernel_launch(void* const* d_in, const int* in_sizes, int n_in,
                              void* d_out, int out_size)
{
    const float* x = (const float*)d_in[0];   // inputs  [B,128]
    const float* w = (const float*)d_in[1];   // kernels [L,128,1]
    const float* b = (const float*)d_in[2];   // biases  [L,128,1]
    float* out = (float*)d_out;

    const int B = in_sizes[0] / CN_D;         // 500000

    const int blocks = 148 * 4;               // one full resident wave
    const int totalWarps = blocks * (256 / 32);

    crossnet_kernel<<<blocks, 256>>>(
        reinterpret_cast<const float4*>(x),
        reinterpret_cast<const float4*>(w),
        reinterpret_cast<const float4*>(b),
        reinterpret_cast<float4*>(out), B, totalWarps);
}

// round 11
// speedup vs baseline: 1.0998x; 1.0998x over previous
#include <cuda_runtime.h>
#include <cuda_bf16.h>

// CrossNet: B=500000, D=128, L=4.   out = alpha_L * x0 + beta_L
//   d_l = w_l·x0 ; alpha_{l+1} = alpha_l*(1+d_l) + c_l ; c_l = w_l·beta_l
//
// R11: R9's best-measured inner body (8-lane row teams -> 3 SHFL/row,
// weights/beta/c in SMEM, 8 rows front-batched = 8 outstanding LDG.128/lane)
// but packaged at R7's granularity: ONE iteration per warp (8-row quantum),
// grid=7813. R9/R10 showed fat per-warp quanta (16 rows) cost 6-9us of
// ragged-tail in harness time; fine blocks schedule better.

#define CN_L  4
#define CN_D  128

__global__ __launch_bounds__(256, 4) void crossnet_kernel(
    const float4* __restrict__ x,     // inputs  [B,128] as float4 [B,32]
    const float4* __restrict__ w4,    // kernels [L,128] as float4
    const float4* __restrict__ b4,    // biases
    float4*       __restrict__ out,
    int B)
{
    __shared__ float4 ws[CN_L * 32];  // weights
    __shared__ float4 sbeta[32];      // beta_L
    __shared__ float  sc[CN_L];       // c_l

    const int tid = threadIdx.x;
    if (tid < CN_L * 32) ws[tid] = w4[tid];
    __syncthreads();

    // warp 0: compute beta_L and c_l into smem
    if (tid < 32) {
        const int ln = tid;
        float4 bt = make_float4(0.f, 0.f, 0.f, 0.f);
#pragma unroll
        for (int l = 0; l < CN_L; ++l) {
            const float4 wl = ws[l * 32 + ln];
            float p = wl.x * bt.x;
            p = fmaf(wl.y, bt.y, p);
            p = fmaf(wl.z, bt.z, p);
            p = fmaf(wl.w, bt.w, p);
#pragma unroll
            for (int off = 16; off > 0; off >>= 1)
                p += __shfl_xor_sync(0xffffffffu, p, off);
            if (ln == 0) sc[l] = p;
            const float4 bl = __ldg(&b4[l * 32 + ln]);
            bt.x += bl.x; bt.y += bl.y; bt.z += bl.z; bt.w += bl.w;
        }
        sbeta[ln] = bt;
    }
    __syncthreads();

    const int warp = (blockIdx.x * blockDim.x + tid) >> 5;
    const int lane = tid & 31;
    const int sub  = lane >> 3;     // row within 4-row group (0..3)
    const int li   = lane & 7;      // lane within 8-lane row team

    const long long row0 = (long long)warp * 8;   // 8 rows per warp
    if (row0 >= B) return;

    const long long rA = row0 + sub;        // sub-group A row
    const long long rB = rA + 4;            // sub-group B row
    const bool okA = rA < B;
    const bool okB = rB < B;

    // 8 independent LDG.128 per lane, all front-batched
    float4 xa[4], xb[4];
#pragma unroll
    for (int i = 0; i < 4; ++i)
        xa[i] = okA ? __ldcs(&x[rA * 32 + i * 8 + li])
                    : make_float4(0.f, 0.f, 0.f, 0.f);
#pragma unroll
    for (int i = 0; i < 4; ++i)
        xb[i] = okB ? __ldcs(&x[rB * 32 + i * 8 + li])
                    : make_float4(0.f, 0.f, 0.f, 0.f);

    // partial dots d_l = w_l·x0 over this lane's 16 cols (weights from smem)
    float pa[CN_L], pb[CN_L];
#pragma unroll
    for (int l = 0; l < CN_L; ++l) {
        float qa = 0.f, qb = 0.f;
#pragma unroll
        for (int i = 0; i < 4; ++i) {
            const float4 wv = ws[l * 32 + i * 8 + li];
            qa = fmaf(wv.x, xa[i].x, qa);  qb = fmaf(wv.x, xb[i].x, qb);
            qa = fmaf(wv.y, xa[i].y, qa);  qb = fmaf(wv.y, xb[i].y, qb);
            qa = fmaf(wv.z, xa[i].z, qa);  qb = fmaf(wv.z, xb[i].z, qb);
            qa = fmaf(wv.w, xa[i].w, qa);  qb = fmaf(wv.w, xb[i].w, qb);
        }
        pa[l] = qa; pb[l] = qb;
    }
    // 3-level butterfly within 8-lane teams; each SHFL serves 4 rows
#pragma unroll
    for (int off = 1; off < 8; off <<= 1) {
#pragma unroll
        for (int l = 0; l < CN_L; ++l) {
            pa[l] += __shfl_xor_sync(0xffffffffu, pa[l], off);
            pb[l] += __shfl_xor_sync(0xffffffffu, pb[l], off);
        }
    }

    // scalar alpha recurrences
    float aA = 1.0f, aB = 1.0f;
#pragma unroll
    for (int l = 0; l < CN_L; ++l) {
        const float cl = sc[l];
        aA = fmaf(aA, pa[l], aA + cl);
        aB = fmaf(aB, pb[l], aB + cl);
    }

    // epilogue
#pragma unroll
    for (int i = 0; i < 4; ++i) {
        const float4 bt = sbeta[i * 8 + li];
        if (okA) {
            float4 o;
            o.x = fmaf(xa[i].x, aA, bt.x);
            o.y = fmaf(xa[i].y, aA, bt.y);
            o.z = fmaf(xa[i].z, aA, bt.z);
            o.w = fmaf(xa[i].w, aA, bt.w);
            __stcs(&out[rA * 32 + i * 8 + li], o);
        }
        if (okB) {
            float4 o;
            o.x = fmaf(xb[i].x, aB, bt.x);
            o.y = fmaf(xb[i].y, aB, bt.y);
            o.z = fmaf(xb[i].z, aB, bt.z);
            o.w = fmaf(xb[i].w, aB, bt.w);
            __stcs(&out[rB * 32 + i * 8 + li], o);
        }
    }
}

extern "C" void kernel_launch(void* const* d_in, const int* in_sizes, int n_in,
                              void* d_out, int out_size)
{
    const float* x = (const float*)d_in[0];   // inputs  [B,128]
    const float* w = (const float*)d_in[1];   // kernels [L,128,1]
    const float* b = (const float*)d_in[2];   // biases  [L,128,1]
    float* out = (float*)d_out;

    const int B = in_sizes[0] / CN_D;                       // 500000
    const long long warps_needed = ((long long)B + 7) / 8;  // 62500
    const int warps_per_block = 256 / 32;
    const int grid = (int)((warps_needed + warps_per_block - 1) / warps_per_block);

    crossnet_kernel<<<grid, 256>>>(
        reinterpret_cast<const float4*>(x),
        reinterpret_cast<const float4*>(w),
        reinterpret_cast<const float4*>(b),
        reinterpret_cast<float4*>(out), B);
}